// round 2
// baseline (speedup 1.0000x reference)
#include <cuda_runtime.h>
#include <cstdint>

#define M_GT 128
#define TPB 128
#define MAX_NB 2048                     // supports N up to 262144
#define MAX_N (MAX_NB * TPB)

// Scratch (allocation-free: __device__ globals)
__device__ float g_maxiou[MAX_N];
__device__ int   g_argmax[MAX_N];
__device__ unsigned long long g_part[M_GT * MAX_NB]; // per-(gt, block) packed best
__device__ unsigned g_forced[M_GT];                  // winning anchor idx per gt

// ---------------- Kernel B: IoU + per-anchor max/argmax + filtered per-gt best ----------------
__global__ __launch_bounds__(TPB) void iou_kernel(const float4* __restrict__ anchors,
                                                  const float4* __restrict__ gtb,
                                                  int N) {
    __shared__ float4 s_gt[M_GT];
    __shared__ float  s_area[M_GT];
    __shared__ unsigned long long s_best[M_GT];

    const int t = threadIdx.x;                 // TPB == M_GT == 128
    {
        float4 g = gtb[t];
        s_gt[t] = g;
        s_area[t] = (g.z - g.x) * (g.w - g.y);
        s_best[t] = 0x00000000FFFFFFFFull;     // iou=0, idx = ~0xFFFFFFFF = 0
    }
    __syncthreads();

    const int i = blockIdx.x * TPB + t;
    if (i < N) {
        float4 a = anchors[i];
        float area_a = (a.z - a.x) * (a.w - a.y);

        float best_iou = -1.0f;                // first gt (even iou=0) updates -> argmax semantics
        int   best_j = 0;
        const unsigned long long nidx = (unsigned long long)(~(unsigned)i);
        const unsigned* hi_words = ((const unsigned*)s_best) + 1;  // high 32 bits, stride 2

        #pragma unroll 4
        for (int m = 0; m < M_GT; m++) {
            float4 g = s_gt[m];
            float lx = fmaxf(a.x, g.x);
            float ly = fmaxf(a.y, g.y);
            float rx = fminf(a.z, g.z);
            float ry = fminf(a.w, g.w);
            float w = fmaxf(rx - lx, 0.0f);
            float h = fmaxf(ry - ly, 0.0f);
            float inter = w * h;
            float uni = (area_a + s_area[m]) - inter;   // same association as reference
            float iou = inter / uni;                    // div.rn: decision-exact vs reference

            if (iou > best_iou) { best_iou = iou; best_j = m; }  // strict > = first-max

            // per-gt argmax: monotonic filter on current best, rare shared atomicMax.
            // ">=" admits exact bit-ties so ~idx packing picks the smaller index,
            // matching argmax(axis=0) first-occurrence. "!=0" avoids the iou==0 storm
            // (init idx 0 already matches the all-zero-column case).
            unsigned bits = __float_as_uint(iou);       // iou >= 0 -> bits order-isomorphic
            unsigned hi = hi_words[2 * m];
            if (bits >= hi && bits != 0u) {
                atomicMax(&s_best[m], ((unsigned long long)bits << 32) | nidx);
            }
        }
        g_maxiou[i] = best_iou;
        g_argmax[i] = best_j;
    }
    __syncthreads();
    g_part[(size_t)t * MAX_NB + blockIdx.x] = s_best[t];
}

// ---------------- Kernel R: reduce per-block winners -> forced anchor per gt ----------------
__global__ void reduce_kernel(int NB) {
    const int m = blockIdx.x;        // 128 blocks x 32 threads
    const int lane = threadIdx.x;
    unsigned long long best = 0x00000000FFFFFFFFull;
    for (int b = lane; b < NB; b += 32) {
        unsigned long long v = g_part[(size_t)m * MAX_NB + b];
        if (v > best) best = v;
    }
    #pragma unroll
    for (int o = 16; o > 0; o >>= 1) {
        unsigned long long v = __shfl_down_sync(0xFFFFFFFFu, best, o);
        if (v > best) best = v;
    }
    if (lane == 0) g_forced[m] = ~(unsigned)(best & 0xFFFFFFFFull);
}

// ---------------- Kernel C: epilogue (masks, labels, box encode, outputs) ----------------
#define TPB_OUT 256
__global__ __launch_bounds__(TPB_OUT) void out_kernel(const float4* __restrict__ anchors,
                                                      const float4* __restrict__ gtb,
                                                      const int* __restrict__ labels,
                                                      float* __restrict__ out,
                                                      int N) {
    __shared__ unsigned s_force[M_GT];
    __shared__ float4   s_gt[M_GT];
    __shared__ int      s_lab[M_GT];

    const int t = threadIdx.x;
    if (t < M_GT) {
        s_force[t] = g_forced[t];
        s_gt[t]    = gtb[t];
        s_lab[t]   = labels[t];
    }
    __syncthreads();

    const int i = blockIdx.x * TPB_OUT + t;
    if (i >= N) return;

    const unsigned ui = (unsigned)i;
    bool forced = false;
    #pragma unroll
    for (int m = 0; m < M_GT; m++) forced |= (s_force[m] == ui);

    float maxiou = g_maxiou[i];
    int   j      = g_argmax[i];

    bool pos = (maxiou >= 0.5f) || forced;
    bool neg = (maxiou < 0.4f) && !pos;
    int  cls = pos ? s_lab[j] : (neg ? 0 : -1);

    float4 a = anchors[i];
    float4 g = s_gt[j];

    const float eps = 1.19209290e-07f;  // FLT_EPSILON == jnp.finfo(float32).eps
    float ax = (a.x + a.z) * 0.5f;
    float ay = (a.y + a.w) * 0.5f;
    float aw = fmaxf(a.z - a.x, eps);
    float ah = fmaxf(a.w - a.y, eps);
    float gx = (g.x + g.z) * 0.5f;
    float gy = (g.y + g.w) * 0.5f;
    float gw = g.z - g.x;
    float gh = g.w - g.y;

    float dx = (gx - ax) / aw;
    float dy = (gy - ay) / ah;
    float dw = logf(gw / aw);
    float dh = logf(gh / ah);

    // output layout (float32): [cls (N)] [reg (N,4)] [pos (N)]
    out[i] = (float)cls;
    float4 r = pos ? make_float4(dx, dy, dw, dh) : make_float4(0.f, 0.f, 0.f, 0.f);
    reinterpret_cast<float4*>(out + N)[i] = r;   // out+N is 16B-aligned (N multiple of 4)
    out[5 * N + i] = pos ? 1.0f : 0.0f;
}

extern "C" void kernel_launch(void* const* d_in, const int* in_sizes, int n_in,
                              void* d_out, int out_size) {
    const float4* anchors = (const float4*)d_in[0];
    const float4* gtb     = (const float4*)d_in[1];
    const int*    labels  = (const int*)d_in[2];
    float* out = (float*)d_out;
    const int N = in_sizes[0] / 4;
    const int NB = (N + TPB - 1) / TPB;

    iou_kernel<<<NB, TPB>>>(anchors, gtb, N);
    reduce_kernel<<<M_GT, 32>>>(NB);
    out_kernel<<<(N + TPB_OUT - 1) / TPB_OUT, TPB_OUT>>>(anchors, gtb, labels, out, N);
}

// round 3
// speedup vs baseline: 1.1598x; 1.1598x over previous
#include <cuda_runtime.h>
#include <cstdint>

#define M_GT 128
#define TPB 256
#define A_PER 4
#define TILE (TPB * A_PER)      // 1024 anchors per block
#define MAX_NB 256              // supports N up to 262144
#define MAX_N 262144

// Scratch (allocation-free: __device__ globals)
__device__ float g_maxiou[MAX_N];
__device__ int   g_argmax[MAX_N];
__device__ unsigned long long g_part[M_GT * MAX_NB]; // per-(gt, block) packed best
__device__ unsigned g_forced[M_GT];                  // winning anchor idx per gt

// ---------------- Kernel B: IoU + per-anchor max/argmax + warp-amortized per-gt best ----------------
__global__ __launch_bounds__(TPB) void iou_kernel(const float4* __restrict__ anchors,
                                                  const float4* __restrict__ gtb,
                                                  int N) {
    __shared__ float4 s_gt[M_GT];
    __shared__ float  s_area[M_GT];
    __shared__ unsigned long long s_best[M_GT];

    const int t = threadIdx.x;
    if (t < M_GT) {
        float4 g = gtb[t];
        s_gt[t] = g;
        s_area[t] = (g.z - g.x) * (g.w - g.y);
        s_best[t] = 0x00000000FFFFFFFFull;   // iou=0, idx = ~0xFFFFFFFF = 0 (all-zero column)
    }
    __syncthreads();

    const int lane = t & 31;
    const int base = blockIdx.x * TILE;

    float4   a[A_PER];
    float    area_a[A_PER];
    bool     val[A_PER];
    unsigned aidx[A_PER];
    #pragma unroll
    for (int k = 0; k < A_PER; k++) {
        int i = base + t + k * TPB;        // increasing index with k (first-tie = smallest k)
        val[k]  = (i < N);
        aidx[k] = (unsigned)i;
        float4 av = anchors[val[k] ? i : 0];
        a[k] = av;
        area_a[k] = (av.z - av.x) * (av.w - av.y);
    }

    float best_iou[A_PER];
    int   best_j[A_PER];
    #pragma unroll
    for (int k = 0; k < A_PER; k++) { best_iou[k] = -1.0f; best_j[k] = 0; }

    #pragma unroll 2
    for (int m = 0; m < M_GT; m++) {
        const float4 g  = s_gt[m];
        const float  ab = s_area[m];

        unsigned lbits = 0u;               // this thread's best iou bits for gt m
        unsigned lidx  = 0xFFFFFFFFu;      // its anchor index

        #pragma unroll
        for (int k = 0; k < A_PER; k++) {
            float lx = fmaxf(a[k].x, g.x);
            float ly = fmaxf(a[k].y, g.y);
            float rx = fminf(a[k].z, g.z);
            float ry = fminf(a[k].w, g.w);
            float w = fmaxf(rx - lx, 0.0f);
            float h = fmaxf(ry - ly, 0.0f);
            float inter = w * h;
            float uni = (area_a[k] + ab) - inter;    // same association as reference
            float iou = inter / uni;                 // div.rn: decision-exact vs reference

            if (iou > best_iou[k]) { best_iou[k] = iou; best_j[k] = m; }   // strict > = first-max

            unsigned b = val[k] ? __float_as_uint(iou) : 0u;  // iou >= 0 -> bits monotonic
            if (b > lbits) { lbits = b; lidx = aidx[k]; }     // strict > keeps smallest k on tie
        }

        // per-gt argmax across the warp's 128 anchors (amortized: once per warp per gt)
        unsigned wmax = __reduce_max_sync(0xFFFFFFFFu, lbits);
        if (wmax != 0u) {
            unsigned cand = (lbits == wmax) ? lidx : 0xFFFFFFFFu;
            unsigned widx = __reduce_min_sync(0xFFFFFFFFu, cand);   // first index on tie
            if (lane == 0) {
                atomicMax(&s_best[m],
                          ((unsigned long long)wmax << 32) | (unsigned long long)(~widx));
            }
        }
    }

    #pragma unroll
    for (int k = 0; k < A_PER; k++) {
        if (val[k]) {
            g_maxiou[aidx[k]] = best_iou[k];
            g_argmax[aidx[k]] = best_j[k];
        }
    }

    __syncthreads();
    if (t < M_GT) g_part[(size_t)t * MAX_NB + blockIdx.x] = s_best[t];
}

// ---------------- Kernel R: reduce per-block winners -> forced anchor per gt ----------------
__global__ void reduce_kernel(int NB) {
    const int m = blockIdx.x;        // 128 blocks x 32 threads
    const int lane = threadIdx.x;
    unsigned long long best = 0x00000000FFFFFFFFull;
    for (int b = lane; b < NB; b += 32) {
        unsigned long long v = g_part[(size_t)m * MAX_NB + b];
        if (v > best) best = v;
    }
    #pragma unroll
    for (int o = 16; o > 0; o >>= 1) {
        unsigned long long v = __shfl_down_sync(0xFFFFFFFFu, best, o);
        if (v > best) best = v;
    }
    if (lane == 0) g_forced[m] = ~(unsigned)(best & 0xFFFFFFFFull);
}

// ---------------- Kernel C: epilogue (masks, labels, box encode, outputs) ----------------
#define TPB_OUT 256
__global__ __launch_bounds__(TPB_OUT) void out_kernel(const float4* __restrict__ anchors,
                                                      const float4* __restrict__ gtb,
                                                      const int* __restrict__ labels,
                                                      float* __restrict__ out,
                                                      int N) {
    __shared__ unsigned s_force[M_GT];
    __shared__ float4   s_gt[M_GT];
    __shared__ int      s_lab[M_GT];

    const int t = threadIdx.x;
    if (t < M_GT) {
        s_force[t] = g_forced[t];
        s_gt[t]    = gtb[t];
        s_lab[t]   = labels[t];
    }
    __syncthreads();

    const int i = blockIdx.x * TPB_OUT + t;
    if (i >= N) return;

    const unsigned ui = (unsigned)i;
    bool forced = false;
    #pragma unroll
    for (int m = 0; m < M_GT; m++) forced |= (s_force[m] == ui);

    float maxiou = g_maxiou[i];
    int   j      = g_argmax[i];

    bool pos = (maxiou >= 0.5f) || forced;
    bool neg = (maxiou < 0.4f) && !pos;
    int  cls = pos ? s_lab[j] : (neg ? 0 : -1);

    float4 a = anchors[i];
    float4 g = s_gt[j];

    const float eps = 1.19209290e-07f;  // FLT_EPSILON == jnp.finfo(float32).eps
    float ax = (a.x + a.z) * 0.5f;
    float ay = (a.y + a.w) * 0.5f;
    float aw = fmaxf(a.z - a.x, eps);
    float ah = fmaxf(a.w - a.y, eps);
    float gx = (g.x + g.z) * 0.5f;
    float gy = (g.y + g.w) * 0.5f;
    float gw = g.z - g.x;
    float gh = g.w - g.y;

    float dx = (gx - ax) / aw;
    float dy = (gy - ay) / ah;
    float dw = logf(gw / aw);
    float dh = logf(gh / ah);

    // output layout (float32): [cls (N)] [reg (N,4)] [pos (N)]
    out[i] = (float)cls;
    float4 r = pos ? make_float4(dx, dy, dw, dh) : make_float4(0.f, 0.f, 0.f, 0.f);
    reinterpret_cast<float4*>(out + N)[i] = r;   // out+N is 16B-aligned (N multiple of 4)
    out[5 * N + i] = pos ? 1.0f : 0.0f;
}

extern "C" void kernel_launch(void* const* d_in, const int* in_sizes, int n_in,
                              void* d_out, int out_size) {
    const float4* anchors = (const float4*)d_in[0];
    const float4* gtb     = (const float4*)d_in[1];
    const int*    labels  = (const int*)d_in[2];
    float* out = (float*)d_out;
    const int N = in_sizes[0] / 4;
    const int NB = (N + TILE - 1) / TILE;

    iou_kernel<<<NB, TPB>>>(anchors, gtb, N);
    reduce_kernel<<<M_GT, 32>>>(NB);
    out_kernel<<<(N + TPB_OUT - 1) / TPB_OUT, TPB_OUT>>>(anchors, gtb, labels, out, N);
}

// round 5
// speedup vs baseline: 1.7526x; 1.5111x over previous
#include <cuda_runtime.h>
#include <cstdint>

#define M_GT 128
#define M_CHUNK 64
#define N_MCHUNK 2
#define TPB 256
#define A_PER 2
#define TILE (TPB * A_PER)      // 512 anchors per block
#define MAX_NB 512              // anchor-block columns; supports N up to 262144
#define MAX_N 262144

// Scratch (allocation-free: __device__ globals)
__device__ float g_maxiou[N_MCHUNK][MAX_N];
__device__ int   g_argmax[N_MCHUNK][MAX_N];
__device__ unsigned long long g_part[M_GT][MAX_NB]; // per-(gt, anchor-block) packed best
__device__ unsigned g_forced[M_GT];                 // winning anchor idx per gt

// ---------- Kernel B: 2D grid: x = anchor tile (512), y = gt chunk (64) ----------
__global__ __launch_bounds__(TPB) void iou_kernel(const float4* __restrict__ anchors,
                                                  const float4* __restrict__ gtb,
                                                  int N) {
    __shared__ float4 s_gt[M_CHUNK];
    __shared__ float  s_area[M_CHUNK];
    __shared__ unsigned long long s_best[M_CHUNK];

    const int t = threadIdx.x;
    const int mbase = blockIdx.y * M_CHUNK;
    if (t < M_CHUNK) {
        float4 g = gtb[mbase + t];
        s_gt[t] = g;
        s_area[t] = (g.z - g.x) * (g.w - g.y);
        s_best[t] = 0x00000000FFFFFFFFull;   // iou=0, idx = ~0xFFFFFFFF = 0 (all-zero column)
    }
    __syncthreads();

    const int lane = t & 31;
    const int base = blockIdx.x * TILE;

    float4   a[A_PER];
    float    area_a[A_PER];
    bool     val[A_PER];
    unsigned aidx[A_PER];
    #pragma unroll
    for (int k = 0; k < A_PER; k++) {
        int i = base + t + k * TPB;        // k=0 has the smaller index
        val[k]  = (i < N);
        aidx[k] = (unsigned)i;
        float4 av = anchors[val[k] ? i : 0];
        a[k] = av;
        area_a[k] = (av.z - av.x) * (av.w - av.y);
    }

    float best_iou[A_PER];
    int   best_j[A_PER];                   // local m within chunk
    #pragma unroll
    for (int k = 0; k < A_PER; k++) { best_iou[k] = -1.0f; best_j[k] = 0; }

    #pragma unroll 2
    for (int m = 0; m < M_CHUNK; m++) {
        const float4 g  = s_gt[m];
        const float  ab = s_area[m];

        unsigned bbits[A_PER];
        #pragma unroll
        for (int k = 0; k < A_PER; k++) {
            float lx = fmaxf(a[k].x, g.x);
            float ly = fmaxf(a[k].y, g.y);
            float rx = fminf(a[k].z, g.z);
            float ry = fminf(a[k].w, g.w);
            float w = fmaxf(rx - lx, 0.0f);
            float h = fmaxf(ry - ly, 0.0f);
            float inter = w * h;
            float uni = (area_a[k] + ab) - inter;    // same association as reference
            float iou = inter / uni;                 // div.rn: decision-exact vs reference

            if (iou > best_iou[k]) { best_iou[k] = iou; best_j[k] = m; }  // strict > = first-max
            bbits[k] = val[k] ? __float_as_uint(iou) : 0u;  // iou >= 0 -> bits monotonic
        }

        // lane-local best over its A_PER anchors (strict > keeps k=0 = smaller index on tie)
        unsigned lbits = bbits[0];
        unsigned lidx  = aidx[0];
        if (bbits[1] > lbits) { lbits = bbits[1]; lidx = aidx[1]; }

        // per-gt argmax across the warp's 64 anchors (amortized once per warp per gt)
        unsigned wmax = __reduce_max_sync(0xFFFFFFFFu, lbits);
        if (wmax != 0u) {
            unsigned cand = (lbits == wmax) ? lidx : 0xFFFFFFFFu;
            unsigned widx = __reduce_min_sync(0xFFFFFFFFu, cand);   // first index on tie
            if (lane == 0) {
                atomicMax(&s_best[m],
                          ((unsigned long long)wmax << 32) | (unsigned long long)(~widx));
            }
        }
    }

    const int by = blockIdx.y;
    #pragma unroll
    for (int k = 0; k < A_PER; k++) {
        if (val[k]) {
            g_maxiou[by][aidx[k]] = best_iou[k];
            g_argmax[by][aidx[k]] = best_j[k];   // local m; global offset added at merge
        }
    }

    __syncthreads();
    if (t < M_CHUNK) g_part[mbase + t][blockIdx.x] = s_best[t];
}

// ---------- Kernel R: reduce per-block winners -> forced anchor per gt ----------
__global__ void reduce_kernel(int NB) {
    const int m = blockIdx.x;        // 128 blocks x 32 threads
    const int lane = threadIdx.x;
    unsigned long long best = 0x00000000FFFFFFFFull;
    for (int b = lane; b < NB; b += 32) {
        unsigned long long v = g_part[m][b];
        if (v > best) best = v;
    }
    #pragma unroll
    for (int o = 16; o > 0; o >>= 1) {
        unsigned long long v = __shfl_down_sync(0xFFFFFFFFu, best, o);
        if (v > best) best = v;
    }
    if (lane == 0) g_forced[m] = ~(unsigned)(best & 0xFFFFFFFFull);
}

// ---------- Kernel C: merge halves + epilogue ----------
#define TPB_OUT 256
__global__ __launch_bounds__(TPB_OUT) void out_kernel(const float4* __restrict__ anchors,
                                                      const float4* __restrict__ gtb,
                                                      const int* __restrict__ labels,
                                                      float* __restrict__ out,
                                                      int N) {
    __shared__ unsigned s_force[M_GT];
    __shared__ float4   s_gt[M_GT];
    __shared__ int      s_lab[M_GT];

    const int t = threadIdx.x;
    if (t < M_GT) {
        s_force[t] = g_forced[t];
        s_gt[t]    = gtb[t];
        s_lab[t]   = labels[t];
    }
    __syncthreads();

    const int i = blockIdx.x * TPB_OUT + t;
    if (i >= N) return;

    const unsigned ui = (unsigned)i;
    bool forced = false;
    #pragma unroll
    for (int m = 0; m < M_GT; m++) forced |= (s_force[m] == ui);

    // merge the two gt-chunks: strict > prefers chunk 0 on ties (first-index semantics)
    float m0 = g_maxiou[0][i];
    float m1 = g_maxiou[1][i];
    int   j0 = g_argmax[0][i];
    int   j1 = g_argmax[1][i] + M_CHUNK;
    float maxiou = (m1 > m0) ? m1 : m0;
    int   j      = (m1 > m0) ? j1 : j0;

    bool pos = (maxiou >= 0.5f) || forced;
    bool neg = (maxiou < 0.4f) && !pos;
    int  cls = pos ? s_lab[j] : (neg ? 0 : -1);

    float4 a = anchors[i];
    float4 g = s_gt[j];

    const float eps = 1.19209290e-07f;  // FLT_EPSILON == jnp.finfo(float32).eps
    float ax = (a.x + a.z) * 0.5f;
    float ay = (a.y + a.w) * 0.5f;
    float aw = fmaxf(a.z - a.x, eps);
    float ah = fmaxf(a.w - a.y, eps);
    float gx = (g.x + g.z) * 0.5f;
    float gy = (g.y + g.w) * 0.5f;
    float gw = g.z - g.x;
    float gh = g.w - g.y;

    float dx = (gx - ax) / aw;
    float dy = (gy - ay) / ah;
    float dw = logf(gw / aw);
    float dh = logf(gh / ah);

    // output layout (float32): [cls (N)] [reg (N,4)] [pos (N)]
    out[i] = (float)cls;
    float4 r = pos ? make_float4(dx, dy, dw, dh) : make_float4(0.f, 0.f, 0.f, 0.f);
    reinterpret_cast<float4*>(out + N)[i] = r;   // out+N is 16B-aligned (N multiple of 4)
    out[5 * N + i] = pos ? 1.0f : 0.0f;
}

extern "C" void kernel_launch(void* const* d_in, const int* in_sizes, int n_in,
                              void* d_out, int out_size) {
    const float4* anchors = (const float4*)d_in[0];
    const float4* gtb     = (const float4*)d_in[1];
    const int*    labels  = (const int*)d_in[2];
    float* out = (float*)d_out;
    const int N = in_sizes[0] / 4;
    const int NBx = (N + TILE - 1) / TILE;

    dim3 grid(NBx, N_MCHUNK);
    iou_kernel<<<grid, TPB>>>(anchors, gtb, N);
    reduce_kernel<<<M_GT, 32>>>(NBx);
    out_kernel<<<(N + TPB_OUT - 1) / TPB_OUT, TPB_OUT>>>(anchors, gtb, labels, out, N);
}

// round 7
// speedup vs baseline: 1.8451x; 1.0528x over previous
#include <cuda_runtime.h>
#include <cstdint>

#define M_GT 128
#define M_CHUNK 32
#define N_MCHUNK 4
#define TPB 256
#define A_PER 2
#define TILE (TPB * A_PER)      // 512 anchors per block
#define MAX_NB 512              // anchor-block columns; supports N up to 262144
#define MAX_N 262144

// Scratch (allocation-free: __device__ globals)
__device__ uint2 g_res[N_MCHUNK][MAX_N];            // (iou_bits, local argmax) per anchor per chunk
__device__ unsigned long long g_part[M_GT][MAX_NB]; // per-(gt, anchor-block) packed best
__device__ unsigned g_forced[M_GT];                 // winning anchor idx per gt

// Correctly-rounded fp32 division for normal operands (Markstein fast path, no guard).
// Bit-identical to div.rn for our operand ranges: den in [64, ~1e6], num in {0} U [1e-8, 5e5].
__device__ __forceinline__ float exact_div(float num, float den) {
    float r0; asm("rcp.approx.f32 %0, %1;" : "=f"(r0) : "f"(den));
    float e  = __fmaf_rn(-den, r0, 1.0f);
    float r1 = __fmaf_rn(r0, e, r0);     // refined reciprocal, ~0.5 ulp
    float y  = __fmul_rn(num, r1);
    float rr = __fmaf_rn(-den, y, num);  // exact residual (Sterbenz-range)
    return __fmaf_rn(rr, r1, y);         // final correction -> RN(num/den)
}

// ---------- Kernel B: 2D grid: x = anchor tile (512), y = gt chunk (32) ----------
__global__ __launch_bounds__(TPB) void iou_kernel(const float4* __restrict__ anchors,
                                                  const float4* __restrict__ gtb,
                                                  int N) {
    __shared__ float4 s_gt[M_CHUNK];
    __shared__ float  s_area[M_CHUNK];
    __shared__ unsigned long long s_best[M_CHUNK];

    const int t = threadIdx.x;
    const int mbase = blockIdx.y * M_CHUNK;
    if (t < M_CHUNK) {
        float4 g = gtb[mbase + t];
        s_gt[t] = g;
        s_area[t] = (g.z - g.x) * (g.w - g.y);
        s_best[t] = 0x00000000FFFFFFFFull;   // iou=0, idx = ~0xFFFFFFFF = 0 (all-zero column)
    }
    __syncthreads();

    const int lane = t & 31;
    const int base = blockIdx.x * TILE;

    float4   a[A_PER];
    float    area_a[A_PER];
    bool     val[A_PER];
    unsigned aidx[A_PER];
    #pragma unroll
    for (int k = 0; k < A_PER; k++) {
        int i = base + t + k * TPB;        // k=0 has the smaller index
        val[k]  = (i < N);
        aidx[k] = (unsigned)i;
        float4 av = anchors[val[k] ? i : 0];
        a[k] = av;
        area_a[k] = (av.z - av.x) * (av.w - av.y);
    }

    float best_iou[A_PER];
    int   best_j[A_PER];                   // local m within chunk
    #pragma unroll
    for (int k = 0; k < A_PER; k++) { best_iou[k] = -1.0f; best_j[k] = 0; }

    #pragma unroll 4
    for (int m = 0; m < M_CHUNK; m++) {
        const float4 g  = s_gt[m];
        const float  ab = s_area[m];

        unsigned bbits[A_PER];
        #pragma unroll
        for (int k = 0; k < A_PER; k++) {
            float lx = fmaxf(a[k].x, g.x);
            float ly = fmaxf(a[k].y, g.y);
            float rx = fminf(a[k].z, g.z);
            float ry = fminf(a[k].w, g.w);
            float w = fmaxf(rx - lx, 0.0f);
            float h = fmaxf(ry - ly, 0.0f);
            float inter = w * h;
            float uni = (area_a[k] + ab) - inter;    // same association as reference
            float iou = exact_div(inter, uni);       // == div.rn: decision-exact vs reference

            if (iou > best_iou[k]) { best_iou[k] = iou; best_j[k] = m; }  // strict > = first-max
            bbits[k] = val[k] ? __float_as_uint(iou) : 0u;  // iou >= 0 -> bits monotonic
        }

        // lane-local best (bits tie -> k=0 = smaller index, via ==bbits[0] preference)
        unsigned lbits = bbits[0] >= bbits[1] ? bbits[0] : bbits[1];
        unsigned lidx  = (lbits == bbits[0]) ? aidx[0] : aidx[1];

        // per-gt argmax across the warp's 64 anchors (amortized once per warp per gt)
        unsigned wmax = __reduce_max_sync(0xFFFFFFFFu, lbits);
        if (wmax != 0u) {
            unsigned cand = (lbits == wmax) ? lidx : 0xFFFFFFFFu;
            unsigned widx = __reduce_min_sync(0xFFFFFFFFu, cand);   // first index on tie
            if (lane == 0) {
                atomicMax(&s_best[m],
                          ((unsigned long long)wmax << 32) | (unsigned long long)(~widx));
            }
        }
    }

    const int by = blockIdx.y;
    #pragma unroll
    for (int k = 0; k < A_PER; k++) {
        if (val[k]) {
            g_res[by][aidx[k]] = make_uint2(__float_as_uint(best_iou[k]), (unsigned)best_j[k]);
        }
    }

    __syncthreads();
    if (t < M_CHUNK) g_part[mbase + t][blockIdx.x] = s_best[t];
}

// ---------- Kernel R: reduce per-block winners -> forced anchor per gt ----------
__global__ void reduce_kernel(int NB) {
    const int m = blockIdx.x;        // 128 blocks x 32 threads
    const int lane = threadIdx.x;
    unsigned long long best = 0x00000000FFFFFFFFull;
    for (int b = lane; b < NB; b += 32) {
        unsigned long long v = g_part[m][b];
        if (v > best) best = v;
    }
    #pragma unroll
    for (int o = 16; o > 0; o >>= 1) {
        unsigned long long v = __shfl_down_sync(0xFFFFFFFFu, best, o);
        if (v > best) best = v;
    }
    if (lane == 0) g_forced[m] = ~(unsigned)(best & 0xFFFFFFFFull);
}

// ---------- Kernel C: merge chunks + epilogue ----------
#define TPB_OUT 256
__global__ __launch_bounds__(TPB_OUT) void out_kernel(const float4* __restrict__ anchors,
                                                      const float4* __restrict__ gtb,
                                                      const int* __restrict__ labels,
                                                      float* __restrict__ out,
                                                      int N) {
    __shared__ unsigned s_force[M_GT];
    __shared__ float4   s_gt[M_GT];
    __shared__ int      s_lab[M_GT];

    const int t = threadIdx.x;
    if (t < M_GT) {
        s_force[t] = g_forced[t];
        s_gt[t]    = gtb[t];
        s_lab[t]   = labels[t];
    }
    __syncthreads();

    const int i = blockIdx.x * TPB_OUT + t;
    if (i >= N) return;

    const unsigned ui = (unsigned)i;
    bool forced = false;
    #pragma unroll
    for (int m = 0; m < M_GT; m++) forced |= (s_force[m] == ui);

    // merge gt-chunks: strict > prefers earlier chunk on ties (first-index semantics).
    // stored bits are of iou >= 0 -> unsigned compare is order-correct.
    unsigned bb = 0u; int j = 0;
    #pragma unroll
    for (int c = 0; c < N_MCHUNK; c++) {
        uint2 r = g_res[c][i];
        if (c == 0 || r.x > bb) { bb = r.x; j = (int)r.y + c * M_CHUNK; }
    }
    float maxiou = __uint_as_float(bb);

    bool pos = (maxiou >= 0.5f) || forced;
    bool neg = (maxiou < 0.4f) && !pos;
    int  cls = pos ? s_lab[j] : (neg ? 0 : -1);

    float4 a = anchors[i];
    float4 g = s_gt[j];

    const float eps = 1.19209290e-07f;  // FLT_EPSILON == jnp.finfo(float32).eps
    float ax = (a.x + a.z) * 0.5f;
    float ay = (a.y + a.w) * 0.5f;
    float aw = fmaxf(a.z - a.x, eps);
    float ah = fmaxf(a.w - a.y, eps);
    float gx = (g.x + g.z) * 0.5f;
    float gy = (g.y + g.w) * 0.5f;
    float gw = g.z - g.x;
    float gh = g.w - g.y;

    float dx = (gx - ax) / aw;
    float dy = (gy - ay) / ah;
    float dw = logf(gw / aw);
    float dh = logf(gh / ah);

    // output layout (float32): [cls (N)] [reg (N,4)] [pos (N)]
    out[i] = (float)cls;
    float4 r = pos ? make_float4(dx, dy, dw, dh) : make_float4(0.f, 0.f, 0.f, 0.f);
    reinterpret_cast<float4*>(out + N)[i] = r;   // out+N is 16B-aligned (N multiple of 4)
    out[5 * N + i] = pos ? 1.0f : 0.0f;
}

extern "C" void kernel_launch(void* const* d_in, const int* in_sizes, int n_in,
                              void* d_out, int out_size) {
    const float4* anchors = (const float4*)d_in[0];
    const float4* gtb     = (const float4*)d_in[1];
    const int*    labels  = (const int*)d_in[2];
    float* out = (float*)d_out;
    const int N = in_sizes[0] / 4;
    const int NBx = (N + TILE - 1) / TILE;

    dim3 grid(NBx, N_MCHUNK);
    iou_kernel<<<grid, TPB>>>(anchors, gtb, N);
    reduce_kernel<<<M_GT, 32>>>(NBx);
    out_kernel<<<(N + TPB_OUT - 1) / TPB_OUT, TPB_OUT>>>(anchors, gtb, labels, out, N);
}